// round 11
// baseline (speedup 1.0000x reference)
#include <cuda_runtime.h>
#include <cuda_fp16.h>
#include <cstdint>

#define D 128
#define MAX_N 50176
#define MAX_E 810000
#define ROWP (D + 8)           // padded half-row: 136 halves = 272B

__device__ __half g_hs[(size_t)MAX_N * D];     // half(h * outdeg^-0.5)
__device__ __half g_agg[(size_t)MAX_N * D];    // f16 atomic accumulator
__device__ __half g_wh[D * D];                 // half(W)
__device__ int    g_outdeg[MAX_N];
__device__ int    g_indeg[MAX_N];

// ---------------------------------------------------------------------------
// 1: degree counts (int2-vectorized, both arrays in one pass)
// ---------------------------------------------------------------------------
__global__ void degree_kernel(const int* __restrict__ src,
                              const int* __restrict__ dst, int E) {
    int i = blockIdx.x * blockDim.x + threadIdx.x;
    int e = i * 2;
    if (e + 1 < E) {
        int2 s2 = *reinterpret_cast<const int2*>(src + e);
        int2 d2 = *reinterpret_cast<const int2*>(dst + e);
        atomicAdd(&g_outdeg[s2.x], 1);
        atomicAdd(&g_outdeg[s2.y], 1);
        atomicAdd(&g_indeg[d2.x], 1);
        atomicAdd(&g_indeg[d2.y], 1);
    } else if (e < E) {
        atomicAdd(&g_outdeg[src[e]], 1);
        atomicAdd(&g_indeg[dst[e]], 1);
    }
}

// ---------------------------------------------------------------------------
// 2: W -> f16 (once per launch; result is L2-resident for the GEMM)
// ---------------------------------------------------------------------------
__global__ void wconv_kernel(const float* __restrict__ W) {
    int idx = blockIdx.x * blockDim.x + threadIdx.x;
    if (idx >= D * D / 8) return;
    const float4* wp = reinterpret_cast<const float4*>(W) + (size_t)idx * 2;
    float4 a = wp[0];
    float4 b = wp[1];
    __half2 packs[4];
    packs[0] = __floats2half2_rn(a.x, a.y);
    packs[1] = __floats2half2_rn(a.z, a.w);
    packs[2] = __floats2half2_rn(b.x, b.y);
    packs[3] = __floats2half2_rn(b.z, b.w);
    reinterpret_cast<uint4*>(g_wh)[idx] = *reinterpret_cast<uint4*>(packs);
}

// ---------------------------------------------------------------------------
// 3: g_hs = half(h * outdeg^-0.5)
// ---------------------------------------------------------------------------
__global__ void scale_h_kernel(const float* __restrict__ h, int N) {
    int idx = blockIdx.x * blockDim.x + threadIdx.x;   // over N*16 groups of 8
    if (idx >= N * (D / 8)) return;
    int row = idx >> 4;
    float s = rsqrtf((float)g_outdeg[row]);
    const float4* hp = reinterpret_cast<const float4*>(h) + (size_t)idx * 2;
    float4 a = hp[0];
    float4 b = hp[1];
    __half2 packs[4];
    packs[0] = __floats2half2_rn(a.x * s, a.y * s);
    packs[1] = __floats2half2_rn(a.z * s, a.w * s);
    packs[2] = __floats2half2_rn(b.x * s, b.y * s);
    packs[3] = __floats2half2_rn(b.z * s, b.w * s);
    reinterpret_cast<uint4*>(g_hs)[idx] = *reinterpret_cast<uint4*>(packs);
}

// ---------------------------------------------------------------------------
// 4: edge scatter, 16 lanes/edge, f16x2 vector reduction
// ---------------------------------------------------------------------------
__global__ void scatter_kernel(const int* __restrict__ src,
                               const int* __restrict__ dst,
                               const int* __restrict__ dist, int E) {
    int gid  = blockIdx.x * blockDim.x + threadIdx.x;
    int e    = gid >> 4;
    int lane = gid & 15;
    if (e >= E) return;

    int s  = __ldg(src + e);
    int d  = __ldg(dst + e);
    int di = __ldg(dist + e);

    float w = __int_as_float((127 - di) << 23);   // exact 0.5^di
    __half2 w2 = __float2half2_rn(w);

    uint4 v = reinterpret_cast<const uint4*>(g_hs + (size_t)s * D)[lane];
    __half2* hv = reinterpret_cast<__half2*>(&v);
    hv[0] = __hmul2(hv[0], w2);
    hv[1] = __hmul2(hv[1], w2);
    hv[2] = __hmul2(hv[2], w2);
    hv[3] = __hmul2(hv[3], w2);

    __half* p = g_agg + (size_t)d * D + lane * 8;
    asm volatile("red.global.add.noftz.v4.f16x2 [%0], {%1,%2,%3,%4};"
                 :: "l"(p), "r"(v.x), "r"(v.y), "r"(v.z), "r"(v.w)
                 : "memory");
}

// ---------------------------------------------------------------------------
// 5: tensor-core GEMM: out = (f16(g_agg) @ g_wh) * indeg^-1.5 + bias
// ---------------------------------------------------------------------------
__device__ __forceinline__ uint32_t smem_u32(const void* p) {
    return (uint32_t)__cvta_generic_to_shared(p);
}

__global__ __launch_bounds__(256)
void gemm_kernel(const float* __restrict__ bias, float* __restrict__ out, int N) {
    extern __shared__ __half sm[];
    __half* As = sm;                 // [128][ROWP]
    __half* Ws = sm + 128 * ROWP;    // [k][n] padded
    int tid  = threadIdx.x;
    int row0 = blockIdx.x * 128;

    // Ws <- g_wh (f16, L2-resident): 2048 uint4, 8 per thread
    for (int i = tid; i < D * D / 8; i += 256) {
        int k  = i >> 4;
        int c8 = (i & 15) * 8;
        *reinterpret_cast<uint4*>(Ws + k * ROWP + c8) =
            reinterpret_cast<const uint4*>(g_wh)[i];
    }
    // A tile: raw f16 copy of g_agg rows (scale deferred to epilogue)
    for (int i = tid; i < 128 * (D / 8); i += 256) {
        int m  = i >> 4;
        int c8 = (i & 15) * 8;
        int grow = row0 + m;
        uint4 v = make_uint4(0, 0, 0, 0);
        if (grow < N)
            v = *reinterpret_cast<const uint4*>(g_agg + (size_t)grow * D + c8);
        *reinterpret_cast<uint4*>(As + m * ROWP + c8) = v;
    }
    __syncthreads();

    int wid  = tid >> 5;
    int lane = tid & 31;
    int mrow = wid * 16;

    float acc[16][4];
    #pragma unroll
    for (int nb = 0; nb < 16; nb++)
        #pragma unroll
        for (int j = 0; j < 4; j++) acc[nb][j] = 0.f;

    uint32_t As_u = smem_u32(As);
    uint32_t Ws_u = smem_u32(Ws);
    int lr = lane & 15;
    int lc = (lane >> 4) << 3;
    int bg = lane >> 3;          // 0..3: matrix group for B x4
    int br = lane & 7;

    #pragma unroll
    for (int kk = 0; kk < 8; kk++) {
        uint32_t a_addr = As_u + (uint32_t)(((mrow + lr) * ROWP) + kk * 16 + lc) * 2;
        uint32_t a0, a1, a2, a3;
        asm volatile("ldmatrix.sync.aligned.m8n8.x4.shared.b16 {%0,%1,%2,%3}, [%4];"
                     : "=r"(a0), "=r"(a1), "=r"(a2), "=r"(a3) : "r"(a_addr));
        #pragma unroll
        for (int nb2 = 0; nb2 < 8; nb2++) {
            int brow = kk * 16 + (bg & 1) * 8 + br;
            int bcol = nb2 * 16 + (bg >> 1) * 8;
            uint32_t b_addr = Ws_u + (uint32_t)(brow * ROWP + bcol) * 2;
            uint32_t b0, b1, b2, b3;
            asm volatile("ldmatrix.sync.aligned.m8n8.x4.trans.shared.b16 {%0,%1,%2,%3}, [%4];"
                         : "=r"(b0), "=r"(b1), "=r"(b2), "=r"(b3) : "r"(b_addr));
            asm volatile("mma.sync.aligned.m16n8k16.row.col.f32.f16.f16.f32 "
                         "{%0,%1,%2,%3},{%4,%5,%6,%7},{%8,%9},{%0,%1,%2,%3};"
                         : "+f"(acc[nb2 * 2][0]), "+f"(acc[nb2 * 2][1]),
                           "+f"(acc[nb2 * 2][2]), "+f"(acc[nb2 * 2][3])
                         : "r"(a0), "r"(a1), "r"(a2), "r"(a3), "r"(b0), "r"(b1));
            asm volatile("mma.sync.aligned.m16n8k16.row.col.f32.f16.f16.f32 "
                         "{%0,%1,%2,%3},{%4,%5,%6,%7},{%8,%9},{%0,%1,%2,%3};"
                         : "+f"(acc[nb2 * 2 + 1][0]), "+f"(acc[nb2 * 2 + 1][1]),
                           "+f"(acc[nb2 * 2 + 1][2]), "+f"(acc[nb2 * 2 + 1][3])
                         : "r"(a0), "r"(a1), "r"(a2), "r"(a3), "r"(b2), "r"(b3));
        }
    }

    // epilogue: per-row indeg^-1.5 scale + bias
    int r0 = row0 + mrow + (lane >> 2);
    int r1 = r0 + 8;
    float s0 = 0.f, s1 = 0.f;
    if (r0 < N) { float id = (float)g_indeg[r0]; s0 = rsqrtf(id) / id; }
    if (r1 < N) { float id = (float)g_indeg[r1]; s1 = rsqrtf(id) / id; }

    #pragma unroll
    for (int nb = 0; nb < 16; nb++) {
        int col = nb * 8 + (lane & 3) * 2;
        float b0 = __ldg(bias + col);
        float b1 = __ldg(bias + col + 1);
        if (r0 < N) {
            float2 o = make_float2(acc[nb][0] * s0 + b0, acc[nb][1] * s0 + b1);
            *reinterpret_cast<float2*>(out + (size_t)r0 * D + col) = o;
        }
        if (r1 < N) {
            float2 o = make_float2(acc[nb][2] * s1 + b0, acc[nb][3] * s1 + b1);
            *reinterpret_cast<float2*>(out + (size_t)r1 * D + col) = o;
        }
    }
}

// ---------------------------------------------------------------------------
extern "C" void kernel_launch(void* const* d_in, const int* in_sizes, int n_in,
                              void* d_out, int out_size) {
    const float* h    = (const float*)d_in[0];
    const int*   src  = (const int*)  d_in[1];
    const int*   dst  = (const int*)  d_in[2];
    const int*   dist = (const int*)  d_in[3];
    const float* W    = (const float*)d_in[4];
    const float* bias = (const float*)d_in[5];
    float*       out  = (float*)d_out;

    int N = in_sizes[0] / D;
    int E = in_sizes[1];

    void *agg_p, *od_p, *id_p;
    cudaGetSymbolAddress(&agg_p, g_agg);
    cudaGetSymbolAddress(&od_p,  g_outdeg);
    cudaGetSymbolAddress(&id_p,  g_indeg);
    cudaMemsetAsync(od_p,  0, N * sizeof(int));
    cudaMemsetAsync(id_p,  0, N * sizeof(int));
    cudaMemsetAsync(agg_p, 0, (size_t)N * D * sizeof(__half));

    int dthreads = (E + 1) / 2;
    degree_kernel<<<(dthreads + 255) / 256, 256>>>(src, dst, E);

    wconv_kernel<<<(D * D / 8 + 255) / 256, 256>>>(W);

    scale_h_kernel<<<(N * (D / 8) + 255) / 256, 256>>>(h, N);

    long long sthreads = (long long)E * 16;
    scatter_kernel<<<(unsigned)((sthreads + 255) / 256), 256>>>(src, dst, dist, E);

    int smem_bytes = 2 * 128 * ROWP * sizeof(__half);  // ~68 KB
    cudaFuncSetAttribute(gemm_kernel,
                         cudaFuncAttributeMaxDynamicSharedMemorySize, smem_bytes);
    gemm_kernel<<<(N + 127) / 128, 256, smem_bytes>>>(bias, out, N);
}

// round 12
// speedup vs baseline: 1.0823x; 1.0823x over previous
#include <cuda_runtime.h>
#include <cuda_fp16.h>
#include <cstdint>

#define D 128
#define MAX_N 50176
#define MAX_E 810000
#define ROWP (D + 8)           // padded half-row: 136 halves = 272B

__device__ __half g_hs[(size_t)MAX_N * D];     // half(h * outdeg^-0.5)
__device__ __half g_agg[(size_t)MAX_N * D];    // f16 atomic accumulator
__device__ __half g_wh[D * D];                 // half(W)
__device__ int    g_deg[2 * MAX_N];            // [0,MAX_N): outdeg  [MAX_N,2N): indeg

// ---------------------------------------------------------------------------
// 1: degree counts (int2-vectorized, both arrays in one pass)
// ---------------------------------------------------------------------------
__global__ void degree_kernel(const int* __restrict__ src,
                              const int* __restrict__ dst, int E) {
    int i = blockIdx.x * blockDim.x + threadIdx.x;
    int e = i * 2;
    if (e + 1 < E) {
        int2 s2 = *reinterpret_cast<const int2*>(src + e);
        int2 d2 = *reinterpret_cast<const int2*>(dst + e);
        atomicAdd(&g_deg[s2.x], 1);
        atomicAdd(&g_deg[s2.y], 1);
        atomicAdd(&g_deg[MAX_N + d2.x], 1);
        atomicAdd(&g_deg[MAX_N + d2.y], 1);
    } else if (e < E) {
        atomicAdd(&g_deg[src[e]], 1);
        atomicAdd(&g_deg[MAX_N + dst[e]], 1);
    }
}

// ---------------------------------------------------------------------------
// 2: fused prep: blocks [0, nh) scale h -> f16;  blocks [nh, nh+8) convert W
// ---------------------------------------------------------------------------
__global__ void prep_kernel(const float* __restrict__ h,
                            const float* __restrict__ W, int N, int nh) {
    if ((int)blockIdx.x >= nh) {
        int idx = (blockIdx.x - nh) * blockDim.x + threadIdx.x;
        if (idx >= D * D / 8) return;
        const float4* wp = reinterpret_cast<const float4*>(W) + (size_t)idx * 2;
        float4 a = wp[0];
        float4 b = wp[1];
        __half2 packs[4];
        packs[0] = __floats2half2_rn(a.x, a.y);
        packs[1] = __floats2half2_rn(a.z, a.w);
        packs[2] = __floats2half2_rn(b.x, b.y);
        packs[3] = __floats2half2_rn(b.z, b.w);
        reinterpret_cast<uint4*>(g_wh)[idx] = *reinterpret_cast<uint4*>(packs);
        return;
    }
    int idx = blockIdx.x * blockDim.x + threadIdx.x;   // over N*16 groups of 8
    if (idx >= N * (D / 8)) return;
    int row = idx >> 4;
    float s = rsqrtf((float)g_deg[row]);
    const float4* hp = reinterpret_cast<const float4*>(h) + (size_t)idx * 2;
    float4 a = hp[0];
    float4 b = hp[1];
    __half2 packs[4];
    packs[0] = __floats2half2_rn(a.x * s, a.y * s);
    packs[1] = __floats2half2_rn(a.z * s, a.w * s);
    packs[2] = __floats2half2_rn(b.x * s, b.y * s);
    packs[3] = __floats2half2_rn(b.z * s, b.w * s);
    reinterpret_cast<uint4*>(g_hs)[idx] = *reinterpret_cast<uint4*>(packs);
}

// ---------------------------------------------------------------------------
// 3: edge scatter, 16 lanes/edge, 2 edges per thread (software-pipelined for
//    2x memory-level parallelism), f16x2 vector reduction
// ---------------------------------------------------------------------------
__global__ void scatter_kernel(const int* __restrict__ src,
                               const int* __restrict__ dst,
                               const int* __restrict__ dist, int E, int Ehalf) {
    int gid  = blockIdx.x * blockDim.x + threadIdx.x;
    int e1   = gid >> 4;
    int lane = gid & 15;
    if (e1 >= Ehalf) return;
    int e2 = e1 + Ehalf;
    bool has2 = (e2 < E);

    // phase 1: edge descriptors (independent loads)
    int s1  = __ldg(src + e1);
    int d1  = __ldg(dst + e1);
    int di1 = __ldg(dist + e1);
    int s2 = 0, d2 = 0, di2 = 0;
    if (has2) {
        s2  = __ldg(src + e2);
        d2  = __ldg(dst + e2);
        di2 = __ldg(dist + e2);
    }

    // phase 2: gathers (independent)
    uint4 v1 = reinterpret_cast<const uint4*>(g_hs + (size_t)s1 * D)[lane];
    uint4 v2 = make_uint4(0, 0, 0, 0);
    if (has2)
        v2 = reinterpret_cast<const uint4*>(g_hs + (size_t)s2 * D)[lane];

    // phase 3: scale + reduce
    __half2 w1 = __float2half2_rn(__int_as_float((127 - di1) << 23));
    __half2* hv1 = reinterpret_cast<__half2*>(&v1);
    hv1[0] = __hmul2(hv1[0], w1);
    hv1[1] = __hmul2(hv1[1], w1);
    hv1[2] = __hmul2(hv1[2], w1);
    hv1[3] = __hmul2(hv1[3], w1);
    __half* p1 = g_agg + (size_t)d1 * D + lane * 8;
    asm volatile("red.global.add.noftz.v4.f16x2 [%0], {%1,%2,%3,%4};"
                 :: "l"(p1), "r"(v1.x), "r"(v1.y), "r"(v1.z), "r"(v1.w)
                 : "memory");

    if (has2) {
        __half2 w2 = __float2half2_rn(__int_as_float((127 - di2) << 23));
        __half2* hv2 = reinterpret_cast<__half2*>(&v2);
        hv2[0] = __hmul2(hv2[0], w2);
        hv2[1] = __hmul2(hv2[1], w2);
        hv2[2] = __hmul2(hv2[2], w2);
        hv2[3] = __hmul2(hv2[3], w2);
        __half* p2 = g_agg + (size_t)d2 * D + lane * 8;
        asm volatile("red.global.add.noftz.v4.f16x2 [%0], {%1,%2,%3,%4};"
                     :: "l"(p2), "r"(v2.x), "r"(v2.y), "r"(v2.z), "r"(v2.w)
                     : "memory");
    }
}

// ---------------------------------------------------------------------------
// 4: tensor-core GEMM: out = (f16(g_agg) @ g_wh) * indeg^-1.5 + bias
// ---------------------------------------------------------------------------
__device__ __forceinline__ uint32_t smem_u32(const void* p) {
    return (uint32_t)__cvta_generic_to_shared(p);
}

__global__ __launch_bounds__(256)
void gemm_kernel(const float* __restrict__ bias, float* __restrict__ out, int N) {
    extern __shared__ __half sm[];
    __half* As = sm;                 // [128][ROWP]
    __half* Ws = sm + 128 * ROWP;    // [k][n] padded
    int tid  = threadIdx.x;
    int row0 = blockIdx.x * 128;

    for (int i = tid; i < D * D / 8; i += 256) {
        int k  = i >> 4;
        int c8 = (i & 15) * 8;
        *reinterpret_cast<uint4*>(Ws + k * ROWP + c8) =
            reinterpret_cast<const uint4*>(g_wh)[i];
    }
    for (int i = tid; i < 128 * (D / 8); i += 256) {
        int m  = i >> 4;
        int c8 = (i & 15) * 8;
        int grow = row0 + m;
        uint4 v = make_uint4(0, 0, 0, 0);
        if (grow < N)
            v = *reinterpret_cast<const uint4*>(g_agg + (size_t)grow * D + c8);
        *reinterpret_cast<uint4*>(As + m * ROWP + c8) = v;
    }
    __syncthreads();

    int wid  = tid >> 5;
    int lane = tid & 31;
    int mrow = wid * 16;

    float acc[16][4];
    #pragma unroll
    for (int nb = 0; nb < 16; nb++)
        #pragma unroll
        for (int j = 0; j < 4; j++) acc[nb][j] = 0.f;

    uint32_t As_u = smem_u32(As);
    uint32_t Ws_u = smem_u32(Ws);
    int lr = lane & 15;
    int lc = (lane >> 4) << 3;
    int bg = lane >> 3;
    int br = lane & 7;

    #pragma unroll
    for (int kk = 0; kk < 8; kk++) {
        uint32_t a_addr = As_u + (uint32_t)(((mrow + lr) * ROWP) + kk * 16 + lc) * 2;
        uint32_t a0, a1, a2, a3;
        asm volatile("ldmatrix.sync.aligned.m8n8.x4.shared.b16 {%0,%1,%2,%3}, [%4];"
                     : "=r"(a0), "=r"(a1), "=r"(a2), "=r"(a3) : "r"(a_addr));
        #pragma unroll
        for (int nb2 = 0; nb2 < 8; nb2++) {
            int brow = kk * 16 + (bg & 1) * 8 + br;
            int bcol = nb2 * 16 + (bg >> 1) * 8;
            uint32_t b_addr = Ws_u + (uint32_t)(brow * ROWP + bcol) * 2;
            uint32_t b0, b1, b2, b3;
            asm volatile("ldmatrix.sync.aligned.m8n8.x4.trans.shared.b16 {%0,%1,%2,%3}, [%4];"
                         : "=r"(b0), "=r"(b1), "=r"(b2), "=r"(b3) : "r"(b_addr));
            asm volatile("mma.sync.aligned.m16n8k16.row.col.f32.f16.f16.f32 "
                         "{%0,%1,%2,%3},{%4,%5,%6,%7},{%8,%9},{%0,%1,%2,%3};"
                         : "+f"(acc[nb2 * 2][0]), "+f"(acc[nb2 * 2][1]),
                           "+f"(acc[nb2 * 2][2]), "+f"(acc[nb2 * 2][3])
                         : "r"(a0), "r"(a1), "r"(a2), "r"(a3), "r"(b0), "r"(b1));
            asm volatile("mma.sync.aligned.m16n8k16.row.col.f32.f16.f16.f32 "
                         "{%0,%1,%2,%3},{%4,%5,%6,%7},{%8,%9},{%0,%1,%2,%3};"
                         : "+f"(acc[nb2 * 2 + 1][0]), "+f"(acc[nb2 * 2 + 1][1]),
                           "+f"(acc[nb2 * 2 + 1][2]), "+f"(acc[nb2 * 2 + 1][3])
                         : "r"(a0), "r"(a1), "r"(a2), "r"(a3), "r"(b2), "r"(b3));
        }
    }

    int r0 = row0 + mrow + (lane >> 2);
    int r1 = r0 + 8;
    float s0 = 0.f, s1 = 0.f;
    if (r0 < N) { float id = (float)g_deg[MAX_N + r0]; s0 = rsqrtf(id) / id; }
    if (r1 < N) { float id = (float)g_deg[MAX_N + r1]; s1 = rsqrtf(id) / id; }

    #pragma unroll
    for (int nb = 0; nb < 16; nb++) {
        int col = nb * 8 + (lane & 3) * 2;
        float b0 = __ldg(bias + col);
        float b1 = __ldg(bias + col + 1);
        if (r0 < N) {
            float2 o = make_float2(acc[nb][0] * s0 + b0, acc[nb][1] * s0 + b1);
            *reinterpret_cast<float2*>(out + (size_t)r0 * D + col) = o;
        }
        if (r1 < N) {
            float2 o = make_float2(acc[nb][2] * s1 + b0, acc[nb][3] * s1 + b1);
            *reinterpret_cast<float2*>(out + (size_t)r1 * D + col) = o;
        }
    }
}

// ---------------------------------------------------------------------------
extern "C" void kernel_launch(void* const* d_in, const int* in_sizes, int n_in,
                              void* d_out, int out_size) {
    const float* h    = (const float*)d_in[0];
    const int*   src  = (const int*)  d_in[1];
    const int*   dst  = (const int*)  d_in[2];
    const int*   dist = (const int*)  d_in[3];
    const float* W    = (const float*)d_in[4];
    const float* bias = (const float*)d_in[5];
    float*       out  = (float*)d_out;

    int N = in_sizes[0] / D;
    int E = in_sizes[1];

    void *agg_p, *deg_p;
    cudaGetSymbolAddress(&agg_p, g_agg);
    cudaGetSymbolAddress(&deg_p, g_deg);
    cudaMemsetAsync(deg_p, 0, 2 * MAX_N * sizeof(int));
    cudaMemsetAsync(agg_p, 0, (size_t)N * D * sizeof(__half));

    int dthreads = (E + 1) / 2;
    degree_kernel<<<(dthreads + 255) / 256, 256>>>(src, dst, E);

    int nh = (N * (D / 8) + 255) / 256;
    prep_kernel<<<nh + 8, 256>>>(h, W, N, nh);

    int Ehalf = (E + 1) / 2;
    long long sthreads = (long long)Ehalf * 16;
    scatter_kernel<<<(unsigned)((sthreads + 255) / 256), 256>>>(src, dst, dist, E, Ehalf);

    int smem_bytes = 2 * 128 * ROWP * sizeof(__half);  // ~68 KB
    cudaFuncSetAttribute(gemm_kernel,
                         cudaFuncAttributeMaxDynamicSharedMemorySize, smem_bytes);
    gemm_kernel<<<(N + 127) / 128, 256, smem_bytes>>>(bias, out, N);
}